// round 11
// baseline (speedup 1.0000x reference)
#include <cuda_runtime.h>
#include <cuda_bf16.h>
#include <cstdint>
#include <cstring>

// SpikingLayer: inputs = X @ W^T, then LIF scan.
// KEY CONSTRAINT (learned R6/R7): the LIF threshold makes the test demand the
// reference's fp32 sequential-k FMA summation order bitwise (tensor-core k-tree
// reorder ~1e-7 => tens of spike flips => rel_err ~1.3e-3 FAIL; R2's sequential
// SIMT fp32 chain => rel_err 0.0 PASS).
// So: keep the exact R2 per-output chain, but execute TWO outputs per
// instruction with packed fma.rn.f32x2 (FFMA2) -> same bits, ~2x fp32 rate.
// d_out = U [128,500,1024] ++ S [128,500,1024] (S region doubles as GEMM scratch).

static constexpr int M_ = 64000;   // 128*500
static constexpr int N_ = 1024;
static constexpr int K_ = 700;
static constexpr int B_ = 128;
static constexpr int T_ = 500;
static constexpr int H_ = 1024;

// ---------------------------------------------------------------------------
// packed helpers
// ---------------------------------------------------------------------------
__device__ __forceinline__ unsigned long long ffma2(unsigned long long a,
                                                    unsigned long long b,
                                                    unsigned long long c) {
    unsigned long long d;
    asm("fma.rn.f32x2 %0, %1, %2, %3;" : "=l"(d) : "l"(a), "l"(b), "l"(c));
    return d;
}
__device__ __forceinline__ float2 unpack2(unsigned long long v) {
    float lo, hi;
    asm("mov.b64 {%0, %1}, %2;" : "=f"(lo), "=f"(hi) : "l"(v));
    return make_float2(lo, hi);
}

// ---------------------------------------------------------------------------
// GEMM: C[m,n] = sum_k A[m,k] * W[n,k]  (NT, fp32, sequential-k FMA chains,
// bitwise identical to the round-2 SIMT kernel; 2 n-columns per FFMA2).
// Block 128x128, BK=8, 256 threads, 8x8 outputs/thread (as 8m x 4 n-pairs).
// As2 holds A values DUPLICATED (a,a) so an LDS.128 yields two packed
// duplicate pairs; a-loads are warp-broadcast (lanes share ty). Bs natural:
// an LDS.128 yields two packed (b0,b1) n-pairs.
// ---------------------------------------------------------------------------
__global__ void __launch_bounds__(256) gemm_f32x2_kernel(
    const float* __restrict__ A,   // [M_, K_]  (X)
    const float* __restrict__ W,   // [N_, K_]
    float* __restrict__ C)         // [M_, N_]
{
    __shared__ float As2[8][256];  // [k][2*m]: value duplicated at 2m, 2m+1
    __shared__ float Bs[8][128];   // [k][n]

    const int tid = threadIdx.x;
    const int bm = blockIdx.y * 128;
    const int bn = blockIdx.x * 128;

    // global-load mapping: 256 threads cover 128 rows x 8 k (float4 each)
    const int lr = tid >> 1;         // 0..127
    const int lk = (tid & 1) * 4;    // 0 or 4
    const float* Aptr = A + (size_t)(bm + lr) * K_ + lk;
    const float* Wptr = W + (size_t)(bn + lr) * K_ + lk;

    // compute mapping: 16x16 threads, 8x8 outputs each
    const int ty = tid >> 4;         // rows ty*8 .. ty*8+7
    const int tx = tid & 15;         // cols tx*8 .. tx*8+7

    unsigned long long acc[8][4];    // [m i][n-pair j] ; pair = cols (2j, 2j+1)
    #pragma unroll
    for (int i = 0; i < 8; i++)
        #pragma unroll
        for (int j = 0; j < 4; j++) acc[i][j] = 0ull;

    for (int k0 = 0; k0 < K_; k0 += 8) {
        float4 av, bv;
        if (k0 + lk + 4 <= K_) {   // only tail chunk (k0=696, lk=4) fails
            av = *reinterpret_cast<const float4*>(Aptr + k0);
            bv = *reinterpret_cast<const float4*>(Wptr + k0);
        } else {
            av = make_float4(0.f, 0.f, 0.f, 0.f);
            bv = make_float4(0.f, 0.f, 0.f, 0.f);
        }
        __syncthreads();
        // A stored duplicated: (a, a) at [2m], [2m+1]
        *reinterpret_cast<float2*>(&As2[lk + 0][2 * lr]) = make_float2(av.x, av.x);
        *reinterpret_cast<float2*>(&As2[lk + 1][2 * lr]) = make_float2(av.y, av.y);
        *reinterpret_cast<float2*>(&As2[lk + 2][2 * lr]) = make_float2(av.z, av.z);
        *reinterpret_cast<float2*>(&As2[lk + 3][2 * lr]) = make_float2(av.w, av.w);
        Bs[lk + 0][lr] = bv.x; Bs[lk + 1][lr] = bv.y;
        Bs[lk + 2][lr] = bv.z; Bs[lk + 3][lr] = bv.w;
        __syncthreads();

        #pragma unroll
        for (int kk = 0; kk < 8; kk++) {
            // a: 8 duplicated pairs (broadcast loads — 16 lanes share ty)
            ulonglong2 a01 = *reinterpret_cast<const ulonglong2*>(&As2[kk][ty * 16 + 0]);
            ulonglong2 a23 = *reinterpret_cast<const ulonglong2*>(&As2[kk][ty * 16 + 4]);
            ulonglong2 a45 = *reinterpret_cast<const ulonglong2*>(&As2[kk][ty * 16 + 8]);
            ulonglong2 a67 = *reinterpret_cast<const ulonglong2*>(&As2[kk][ty * 16 + 12]);
            // b: 4 natural n-pairs
            ulonglong2 b03 = *reinterpret_cast<const ulonglong2*>(&Bs[kk][tx * 8 + 0]);
            ulonglong2 b47 = *reinterpret_cast<const ulonglong2*>(&Bs[kk][tx * 8 + 4]);
            const unsigned long long a_[8] = {a01.x, a01.y, a23.x, a23.y,
                                              a45.x, a45.y, a67.x, a67.y};
            const unsigned long long b_[4] = {b03.x, b03.y, b47.x, b47.y};
            #pragma unroll
            for (int i = 0; i < 8; i++)
                #pragma unroll
                for (int j = 0; j < 4; j++)
                    acc[i][j] = ffma2(a_[i], b_[j], acc[i][j]);
        }
    }

    // epilogue: unpack pairs, same addresses/widths as round 2
    #pragma unroll
    for (int i = 0; i < 8; i++) {
        float* crow = C + (size_t)(bm + ty * 8 + i) * N_ + bn + tx * 8;
        float2 p0 = unpack2(acc[i][0]);
        float2 p1 = unpack2(acc[i][1]);
        float2 p2 = unpack2(acc[i][2]);
        float2 p3 = unpack2(acc[i][3]);
        *reinterpret_cast<float4*>(crow)     = make_float4(p0.x, p0.y, p1.x, p1.y);
        *reinterpret_cast<float4*>(crow + 4) = make_float4(p2.x, p2.y, p3.x, p3.y);
    }
}

// ---------------------------------------------------------------------------
// LIF scan, float2 per thread (2 neurons). In-place over the S region
// (read-ahead by 7 iterations guarantees WAR safety within the thread).
// H[t]=PHI*H[t-1]+inp[t-1]; I[t]=GAMMA*I[t-1]+H[t-1];
// U[t]=BETA*(U[t-1]-I[t-1])-S[t-1]; S[t]=(U[t]>1).
// ---------------------------------------------------------------------------
__global__ void __launch_bounds__(256) lif_scan2_kernel(float2* __restrict__ U,
                                                        float2* S) {
    const float PHI = 0.36787944117144233f;   // exp(-1)
    const float GAM = 0.81873075307798182f;   // exp(-0.2)
    const float BET = 0.90483741803595952f;   // exp(-0.1)
    const int P = H_ / 2;                     // 512 float2 per (b,t)
    const int idx = blockIdx.x * 256 + threadIdx.x;  // 0..65535
    const int b = idx >> 9;
    const int h = idx & 511;
    const size_t base = (size_t)b * T_ * P + h;
    float2* Up = U + base;
    float2* Sp = S + base;

    float2 buf[8];
    #pragma unroll
    for (int i = 0; i < 8; i++) buf[i] = Sp[(size_t)i * P];

    Up[0] = make_float2(0.f, 0.f);
    Sp[0] = make_float2(0.f, 0.f);

    float Hx = 0.f, Ix = 0.f, Ux = 0.f, Sx = 0.f;
    float Hy = 0.f, Iy = 0.f, Uy = 0.f, Sy = 0.f;

    for (int t0 = 1; t0 < T_; t0 += 8) {
        #pragma unroll
        for (int u = 0; u < 8; u++) {
            const int t = t0 + u;
            if (t < T_) {
                const float2 inp = buf[u];                        // inputs[t-1]
                if (t + 7 < T_) buf[u] = Sp[(size_t)(t + 7) * P]; // prefetch
                const float Hnx = fmaf(PHI, Hx, inp.x);
                const float Inx = fmaf(GAM, Ix, Hx);
                const float Unx = BET * (Ux - Ix) - Sx;
                const float Snx = (Unx > 1.f) ? 1.f : 0.f;
                const float Hny = fmaf(PHI, Hy, inp.y);
                const float Iny = fmaf(GAM, Iy, Hy);
                const float Uny = BET * (Uy - Iy) - Sy;
                const float Sny = (Uny > 1.f) ? 1.f : 0.f;
                Up[(size_t)t * P] = make_float2(Unx, Uny);
                Sp[(size_t)t * P] = make_float2(Snx, Sny);
                Hx = Hnx; Ix = Inx; Ux = Unx; Sx = Snx;
                Hy = Hny; Iy = Iny; Uy = Uny; Sy = Sny;
            }
        }
    }
}

// ---------------------------------------------------------------------------
extern "C" void kernel_launch(void* const* d_in, const int* in_sizes, int n_in,
                              void* d_out, int out_size) {
    const float* X = (const float*)d_in[0];   // [128, 500, 700]
    const float* W = (const float*)d_in[1];   // [1024, 700]
    float* outU = (float*)d_out;              // [128, 500, 1024]
    float* outS = outU + (size_t)M_ * N_;     // [128, 500, 1024]

    dim3 gemm_grid(N_ / 128, M_ / 128);       // (8, 500)
    gemm_f32x2_kernel<<<gemm_grid, 256>>>(X, W, outS);

    lif_scan2_kernel<<<(B_ * H_ / 2) / 256, 256>>>(
        (float2*)outU, (float2*)outS);
}

// round 12
// speedup vs baseline: 1.1277x; 1.1277x over previous
#include <cuda_runtime.h>
#include <cuda_bf16.h>
#include <cstdint>

// SpikingLayer: inputs = X @ W^T, then LIF scan — FUSED into one kernel.
//
// Constraints learned:
//  R6/R7: the LIF threshold demands the reference's sequential-k fp32 FMA chain
//         bitwise (any k-reorder -> spike flips -> rel_err ~1.3e-3 FAIL).
//  R2:    sequential SIMT fp32 GEMM = rel_err 0.0 and sits AT the FFMA roofline
//         (~2245us). R11: FFMA2 is not a FLOP doubler on sm_103 (regressed).
//  => GEMM math is fixed; the only lever left is hiding the ~260us scan.
//
// This round: one kernel, 4256 blocks. Blocks 0..3999 = GEMM tiles (identical
// math to R2). Blocks 4000..4255 = LIF scan for one batch b each (2 blocks/b),
// spin-waiting on per-b arrival counters. In-order dispatch => scan blocks only
// become resident after every GEMM block has started => no deadlock; early-b
// scans overlap late GEMM waves and read L2-hot tiles.
// d_out = U [128,500,1024] ++ S [128,500,1024] (S region doubles as GEMM scratch).

static constexpr int M_ = 64000;   // 128*500
static constexpr int N_ = 1024;
static constexpr int K_ = 700;
static constexpr int B_ = 128;
static constexpr int T_ = 500;
static constexpr int H_ = 1024;

static constexpr int GEMM_BLOCKS = (M_ / 128) * (N_ / 128);  // 500*8 = 4000
static constexpr int SCAN_BLOCKS = 256;                      // 2 per batch

__device__ int g_cnt[B_];   // per-batch GEMM-tile arrival counters

__global__ void zero_cnt_kernel() {
    if (threadIdx.x < B_) g_cnt[threadIdx.x] = 0;
}

// ---------------------------------------------------------------------------
// Fused kernel
// ---------------------------------------------------------------------------
__global__ void __launch_bounds__(256) fused_kernel(
    const float* __restrict__ A,   // X  [M_, K_]
    const float* __restrict__ W,   // W  [N_, K_]
    float* __restrict__ U,         // [B_, T_, H_]
    float* S)                      // [B_, T_, H_] : GEMM C output, then in-place spikes
{
    const int id = blockIdx.x;
    const int tid = threadIdx.x;

    if (id < GEMM_BLOCKS) {
        // ================= GEMM role (bitwise-identical to round 2) =========
        __shared__ float As[8][128];
        __shared__ float Bs[8][128];

        const int my = id >> 3;          // 0..499
        const int nx = id & 7;           // 0..7
        const int bm = my * 128;
        const int bn = nx * 128;

        const int lr = tid >> 1;         // 0..127
        const int lk = (tid & 1) * 4;    // 0 or 4
        const float* Aptr = A + (size_t)(bm + lr) * K_ + lk;
        const float* Wptr = W + (size_t)(bn + lr) * K_ + lk;

        const int ty = tid >> 4;         // rows ty*8..ty*8+7
        const int tx = tid & 15;         // cols tx*8..tx*8+7

        float acc[8][8];
        #pragma unroll
        for (int i = 0; i < 8; i++)
            #pragma unroll
            for (int j = 0; j < 8; j++) acc[i][j] = 0.0f;

        for (int k0 = 0; k0 < K_; k0 += 8) {
            float4 av, bv;
            if (k0 + lk + 4 <= K_) {   // only tail chunk (k0=696, lk=4) fails
                av = *reinterpret_cast<const float4*>(Aptr + k0);
                bv = *reinterpret_cast<const float4*>(Wptr + k0);
            } else {
                av = make_float4(0.f, 0.f, 0.f, 0.f);
                bv = make_float4(0.f, 0.f, 0.f, 0.f);
            }
            __syncthreads();
            As[lk + 0][lr] = av.x; As[lk + 1][lr] = av.y;
            As[lk + 2][lr] = av.z; As[lk + 3][lr] = av.w;
            Bs[lk + 0][lr] = bv.x; Bs[lk + 1][lr] = bv.y;
            Bs[lk + 2][lr] = bv.z; Bs[lk + 3][lr] = bv.w;
            __syncthreads();

            #pragma unroll
            for (int kk = 0; kk < 8; kk++) {
                float ar[8], br[8];
                *reinterpret_cast<float4*>(&ar[0]) =
                    *reinterpret_cast<const float4*>(&As[kk][ty * 8]);
                *reinterpret_cast<float4*>(&ar[4]) =
                    *reinterpret_cast<const float4*>(&As[kk][ty * 8 + 4]);
                *reinterpret_cast<float4*>(&br[0]) =
                    *reinterpret_cast<const float4*>(&Bs[kk][tx * 8]);
                *reinterpret_cast<float4*>(&br[4]) =
                    *reinterpret_cast<const float4*>(&Bs[kk][tx * 8 + 4]);
                #pragma unroll
                for (int i = 0; i < 8; i++)
                    #pragma unroll
                    for (int j = 0; j < 8; j++)
                        acc[i][j] = fmaf(ar[i], br[j], acc[i][j]);
            }
        }

        // epilogue into S (the inputs scratch region)
        #pragma unroll
        for (int i = 0; i < 8; i++) {
            float* crow = S + (size_t)(bm + ty * 8 + i) * N_ + bn + tx * 8;
            *reinterpret_cast<float4*>(crow) =
                make_float4(acc[i][0], acc[i][1], acc[i][2], acc[i][3]);
            *reinterpret_cast<float4*>(crow + 4) =
                make_float4(acc[i][4], acc[i][5], acc[i][6], acc[i][7]);
        }

        // publish: all stores visible, then bump every batch this tile touches
        __threadfence();
        __syncthreads();
        if (tid == 0) {
            const int b_lo = (my * 128) / T_;
            const int b_hi = (my * 128 + 127) / T_;
            for (int b = b_lo; b <= b_hi; b++)
                atomicAdd(&g_cnt[b], 1);
        }
    } else {
        // ================= scan role =======================================
        const int sid = id - GEMM_BLOCKS;        // 0..255
        const int b = sid >> 1;                  // 2 blocks per batch

        // wait for all GEMM tiles covering batch b
        if (tid == 0) {
            const int my_lo = (b * T_) / 128;
            const int my_hi = (b * T_ + T_ - 1) / 128;
            const int target = (my_hi - my_lo + 1) * 8;
            while (atomicAdd(&g_cnt[b], 0) < target) __nanosleep(128);
            __threadfence();
        }
        __syncthreads();

        const float PHI = 0.36787944117144233f;   // exp(-1)
        const float GAM = 0.81873075307798182f;   // exp(-0.2)
        const float BET = 0.90483741803595952f;   // exp(-0.1)
        const int P = H_ / 2;                     // 512 float2 per (b,t)

        float2* Uv = reinterpret_cast<float2*>(U);
        float2* Sv = reinterpret_cast<float2*>(S);
        const int idx = sid * 256 + tid;          // 0..65535
        const int h = idx & 511;
        const size_t base = (size_t)b * T_ * P + h;
        float2* Up = Uv + base;
        float2* Sp = Sv + base;

        float2 buf[8];
        #pragma unroll
        for (int i = 0; i < 8; i++) buf[i] = Sp[(size_t)i * P];

        Up[0] = make_float2(0.f, 0.f);
        Sp[0] = make_float2(0.f, 0.f);

        float Hx = 0.f, Ix = 0.f, Ux = 0.f, Sx = 0.f;
        float Hy = 0.f, Iy = 0.f, Uy = 0.f, Sy = 0.f;

        for (int t0 = 1; t0 < T_; t0 += 8) {
            #pragma unroll
            for (int u = 0; u < 8; u++) {
                const int t = t0 + u;
                if (t < T_) {
                    const float2 inp = buf[u];                        // inputs[t-1]
                    if (t + 7 < T_) buf[u] = Sp[(size_t)(t + 7) * P]; // prefetch
                    const float Hnx = fmaf(PHI, Hx, inp.x);
                    const float Inx = fmaf(GAM, Ix, Hx);
                    const float Unx = BET * (Ux - Ix) - Sx;
                    const float Snx = (Unx > 1.f) ? 1.f : 0.f;
                    const float Hny = fmaf(PHI, Hy, inp.y);
                    const float Iny = fmaf(GAM, Iy, Hy);
                    const float Uny = BET * (Uy - Iy) - Sy;
                    const float Sny = (Uny > 1.f) ? 1.f : 0.f;
                    Up[(size_t)t * P] = make_float2(Unx, Uny);
                    Sp[(size_t)t * P] = make_float2(Snx, Sny);
                    Hx = Hnx; Ix = Inx; Ux = Unx; Sx = Snx;
                    Hy = Hny; Iy = Iny; Uy = Uny; Sy = Sny;
                }
            }
        }
    }
}

// ---------------------------------------------------------------------------
extern "C" void kernel_launch(void* const* d_in, const int* in_sizes, int n_in,
                              void* d_out, int out_size) {
    const float* X = (const float*)d_in[0];   // [128, 500, 700]
    const float* W = (const float*)d_in[1];   // [1024, 700]
    float* outU = (float*)d_out;              // [128, 500, 1024]
    float* outS = outU + (size_t)M_ * N_;     // [128, 500, 1024]

    zero_cnt_kernel<<<1, 128>>>();
    fused_kernel<<<GEMM_BLOCKS + SCAN_BLOCKS, 256>>>(X, W, outU, outS);
}